// round 7
// baseline (speedup 1.0000x reference)
#include <cuda_runtime.h>
#include <cuda_fp16.h>
#include <math.h>
#include <mma.h>
using namespace nvcuda;

#define NN 50000
#define EE 800000
#define DD 96
#define CC 40
#define NITE 8
#define SMOOTH 0.5f

#define NBLK 148          // persistent grid: one block per SM
#define NTHR 512          // 16 warps
#define NWARP (NBLK * 16) // 2368 warps
#define NBANDS ((NN + 15) / 16)          // 3125 16-row GEMM bands
#define HPAD (NBANDS * 16)               // 50000 -> 50000 (NN % 16 == 0)
#define LDW 104           // padded half ld for W smem

// ---------------- scratch (device globals; no allocation allowed) ------------
__device__ float  g_h[NN * DD];          // fp32 master features
__device__ __half g_h16[HPAD * DD];      // fp16 mirror for tensor-core A
__device__ __half g_W16[DD * DD];        // fp16 W_gc
__device__ float  g_support32[HPAD * DD];// GEMM out (fp32) / agg gather in
__device__ int    g_count[NN];
__device__ int    g_rowstart[NN + 1];
__device__ int    g_fill[NN];
__device__ int2   g_edge[EE];            // CSR: {src col, f32 val}

__device__ unsigned g_bar_arrive;        // zero-init
__device__ volatile unsigned g_bar_gen;  // zero-init, monotonic

// packed f32x2 FMA
__device__ __forceinline__ void ffma2f(float2& d, float2 a, float2 b) {
    unsigned long long dd = *(unsigned long long*)&d;
    asm("fma.rn.f32x2 %0, %1, %2, %0;"
        : "+l"(dd) : "l"(*(unsigned long long*)&a), "l"(*(unsigned long long*)&b));
    d = *(float2*)&dd;
}

// sense-reversing grid barrier (all NBLK blocks are resident by construction)
__device__ __forceinline__ void grid_sync() {
    __syncthreads();
    if (threadIdx.x == 0) {
        __threadfence();
        unsigned gen = g_bar_gen;
        if (atomicAdd(&g_bar_arrive, 1u) == NBLK - 1) {
            g_bar_arrive = 0;
            __threadfence();
            g_bar_gen = gen + 1;
        } else {
            while (g_bar_gen == gen) {}
            __threadfence();
        }
    }
    __syncthreads();
}

// ---------------- init: h = x (fp32+fp16), W16, zero counts ------------------
__global__ void init_kernel(const float* __restrict__ x, const float* __restrict__ W) {
    int i = blockIdx.x * blockDim.x + threadIdx.x;
    if (i < NN * DD) { float v = x[i]; g_h[i] = v; g_h16[i] = __float2half(v); }
    if (i < DD * DD) g_W16[i] = __float2half(W[i]);
    if (i < NN) g_count[i] = 0;
}

// ---------------- CSR build --------------------------------------------------
__global__ void hist_kernel(const int* __restrict__ erow) {
    int e = blockIdx.x * blockDim.x + threadIdx.x;
    if (e < EE) atomicAdd(&g_count[erow[e]], 1);
}

__global__ void scan_kernel() {
    __shared__ int part[1024];
    const int CH = (NN + 1023) / 1024;
    int t = threadIdx.x;
    int begin = t * CH;
    int end = begin + CH; if (end > NN) end = NN;
    int s = 0;
    for (int i = begin; i < end; ++i) s += g_count[i];
    part[t] = s;
    __syncthreads();
    for (int off = 1; off < 1024; off <<= 1) {
        int v = (t >= off) ? part[t - off] : 0;
        __syncthreads();
        part[t] += v;
        __syncthreads();
    }
    int running = (t == 0) ? 0 : part[t - 1];
    for (int i = begin; i < end; ++i) {
        g_rowstart[i] = running;
        g_fill[i] = running;
        running += g_count[i];
    }
    if (t == 1023) g_rowstart[NN] = running;  // == EE
}

__global__ void fill_kernel(const int* __restrict__ erow,
                            const int* __restrict__ ecol,
                            const float* __restrict__ ev) {
    int e = blockIdx.x * blockDim.x + threadIdx.x;
    if (e < EE) {
        int r = erow[e];
        int p = atomicAdd(&g_fill[r], 1);
        g_edge[p] = make_int2(ecol[e], __float_as_int(ev[e]));
    }
}

// ---------------- fused 8-iteration GCN loop (persistent) --------------------
// Phase 1 (GEMM): warp = 16-row band; A frags from global h16, B from smem W,
//                 fp32 accs stored straight to g_support32 (ld = DD).
// Phase 2 (AGG):  warp = row; 4 edge-groups x 8 feature lanes, float4 gathers.
__global__ void __launch_bounds__(NTHR, 1) fused_kernel(const float* __restrict__ b) {
    __shared__ __half Ws[DD * LDW];
    int tid = threadIdx.x, wid = tid >> 5, lane = tid & 31;
    int bid = blockIdx.x;
    int gwarp = bid * 16 + wid;

    // stage W16 once for the whole kernel
    for (int i = tid; i < DD * DD / 8; i += NTHR) {
        int r = (i * 8) / DD, c = (i * 8) % DD;
        *(uint4*)&Ws[r * LDW + c] = *(const uint4*)&g_W16[r * DD + c];
    }
    __syncthreads();

    int grp = lane >> 3;   // agg: edge group 0..3
    int sub = lane & 7;    // agg: feature-owner lane 0..7

    for (int it = 0; it < NITE; ++it) {
        // ---------------- GEMM phase ----------------
        for (int band = gwarp; band < NBANDS; band += NWARP) {
            const __half* Abase = g_h16 + (size_t)band * 16 * DD;
            float* Obase = g_support32 + (size_t)band * 16 * DD;

            wmma::fragment<wmma::accumulator, 16, 16, 16, float> acc[6];
#pragma unroll
            for (int n = 0; n < 6; ++n) wmma::fill_fragment(acc[n], 0.f);
#pragma unroll
            for (int k = 0; k < 6; ++k) {
                wmma::fragment<wmma::matrix_a, 16, 16, 16, __half, wmma::row_major> af;
                wmma::load_matrix_sync(af, Abase + k * 16, DD);
#pragma unroll
                for (int n = 0; n < 6; ++n) {
                    wmma::fragment<wmma::matrix_b, 16, 16, 16, __half, wmma::row_major> bf;
                    wmma::load_matrix_sync(bf, Ws + (k * 16) * LDW + n * 16, LDW);
                    wmma::mma_sync(acc[n], af, bf, acc[n]);
                }
            }
#pragma unroll
            for (int n = 0; n < 6; ++n)
                wmma::store_matrix_sync(Obase + n * 16, acc[n], DD, wmma::mem_row_major);
        }
        grid_sync();

        // ---------------- AGG phase -----------------
        for (int row = gwarp; row < NN; row += NWARP) {
            int j0 = g_rowstart[row];
            int j1 = g_rowstart[row + 1];

            float2 acc[6];
#pragma unroll
            for (int i = 0; i < 6; ++i) acc[i] = make_float2(0.f, 0.f);

            for (int j = j0 + grp; j < j1; j += 4) {
                int2 e = __ldg(&g_edge[j]);
                float v = __int_as_float(e.y);
                float2 vv = make_float2(v, v);
                const float4* s = (const float4*)(g_support32 + (size_t)e.x * DD);
                float4 d0 = __ldg(&s[sub]);        // feats 4*sub .. +3
                float4 d1 = __ldg(&s[8 + sub]);    // feats 32+4*sub ..
                float4 d2 = __ldg(&s[16 + sub]);   // feats 64+4*sub ..
                ffma2f(acc[0], make_float2(d0.x, d0.y), vv);
                ffma2f(acc[1], make_float2(d0.z, d0.w), vv);
                ffma2f(acc[2], make_float2(d1.x, d1.y), vv);
                ffma2f(acc[3], make_float2(d1.z, d1.w), vv);
                ffma2f(acc[4], make_float2(d2.x, d2.y), vv);
                ffma2f(acc[5], make_float2(d2.z, d2.w), vv);
            }

#pragma unroll
            for (int i = 0; i < 6; ++i) {
                acc[i].x += __shfl_xor_sync(0xffffffffu, acc[i].x, 8);
                acc[i].y += __shfl_xor_sync(0xffffffffu, acc[i].y, 8);
                acc[i].x += __shfl_xor_sync(0xffffffffu, acc[i].x, 16);
                acc[i].y += __shfl_xor_sync(0xffffffffu, acc[i].y, 16);
            }

            if (lane < 8) {
                float* hrow = g_h + (size_t)row * DD;
#pragma unroll
                for (int sg = 0; sg < 3; ++sg) {
                    int off = sg * 32 + sub * 4;
                    float4 hv = *(float4*)&hrow[off];
                    float4 bv = *(const float4*)&b[off];
                    float2 a0 = acc[2 * sg];
                    float2 a1 = acc[2 * sg + 1];
                    hv.x = fmaxf(SMOOTH * hv.x + (1.f - SMOOTH) * (a0.x + bv.x), 0.f);
                    hv.y = fmaxf(SMOOTH * hv.y + (1.f - SMOOTH) * (a0.y + bv.y), 0.f);
                    hv.z = fmaxf(SMOOTH * hv.z + (1.f - SMOOTH) * (a1.x + bv.z), 0.f);
                    hv.w = fmaxf(SMOOTH * hv.w + (1.f - SMOOTH) * (a1.y + bv.w), 0.f);
                    *(float4*)&hrow[off] = hv;
                    __half2 p0 = __floats2half2_rn(hv.x, hv.y);
                    __half2 p1 = __floats2half2_rn(hv.z, hv.w);
                    uint2 u; u.x = *(unsigned*)&p0; u.y = *(unsigned*)&p1;
                    *(uint2*)&g_h16[(size_t)row * DD + off] = u;
                }
            }
        }
        if (it < NITE - 1) grid_sync();
    }
}

// ---------------- final: logits = h @ W_lin, log_softmax ---------------------
__global__ void __launch_bounds__(256) out_kernel(const float* __restrict__ Wl,
                                                  float* __restrict__ out) {
    __shared__ float Ws2[DD * CC];
    __shared__ float Hs[32 * DD];
    __shared__ float Ls[32 * CC];
    int tid = threadIdx.x;
    int row0 = blockIdx.x * 32;

    for (int i = tid; i < DD * CC; i += 256) Ws2[i] = Wl[i];
    for (int i = tid; i < 32 * DD; i += 256) {
        int r = row0 + i / DD;
        Hs[i] = (r < NN) ? g_h[r * DD + (i % DD)] : 0.f;
    }
    __syncthreads();

    for (int o = tid; o < 32 * CC; o += 256) {
        int r = o / CC, c = o % CC;
        float a = 0.f;
#pragma unroll 4
        for (int k = 0; k < DD; ++k) a += Hs[r * DD + k] * Ws2[k * CC + c];
        Ls[o] = a;
    }
    __syncthreads();

    if (tid < 32) {
        int r = row0 + tid;
        if (r < NN) {
            float m = -1e30f;
#pragma unroll
            for (int c = 0; c < CC; ++c) m = fmaxf(m, Ls[tid * CC + c]);
            float s = 0.f;
#pragma unroll
            for (int c = 0; c < CC; ++c) s += expf(Ls[tid * CC + c] - m);
            float lse = m + logf(s);
#pragma unroll
            for (int c = 0; c < CC; ++c) out[r * CC + c] = Ls[tid * CC + c] - lse;
        }
    }
}

// ---------------- launch ------------------------------------------------------
extern "C" void kernel_launch(void* const* d_in, const int* in_sizes, int n_in,
                              void* d_out, int out_size) {
    (void)in_sizes; (void)n_in; (void)out_size;
    const float* x    = (const float*)d_in[0];
    const int*   erow = (const int*)d_in[1];
    const int*   ecol = (const int*)d_in[2];
    const float* ev   = (const float*)d_in[3];
    const float* Wgc  = (const float*)d_in[4];
    const float* bgc  = (const float*)d_in[5];
    const float* Wlin = (const float*)d_in[6];
    float* out = (float*)d_out;

    init_kernel<<<(NN * DD + 255) / 256, 256>>>(x, Wgc);
    hist_kernel<<<(EE + 255) / 256, 256>>>(erow);
    scan_kernel<<<1, 1024>>>();
    fill_kernel<<<(EE + 255) / 256, 256>>>(erow, ecol, ev);

    fused_kernel<<<NBLK, NTHR>>>(bgc);

    out_kernel<<<(NN + 31) / 32, 256>>>(Wlin, out);
}

// round 8
// speedup vs baseline: 1.5173x; 1.5173x over previous
#include <cuda_runtime.h>
#include <cuda_fp16.h>
#include <math.h>
#include <mma.h>
using namespace nvcuda;

#define NN 50000
#define EE 800000
#define DD 96
#define CC 40
#define NITE 8
#define SMOOTH 0.5f

#define NBANDS ((NN + 15) / 16)   // 3125 (NN % 16 == 0)
#define LDW 104                   // padded half ld for W smem

// ---------------- scratch (device globals; no allocation allowed) ------------
__device__ float  g_h[NN * DD];            // fp32 master features
__device__ __half g_h16[NN * DD];          // fp16 mirror (tensor-core A operand)
__device__ __half g_W16[DD * DD];          // fp16 W_gc
__device__ float  g_support32[NN * DD];    // GEMM out (fp32) / agg gather in
__device__ int    g_count[NN];             // zero at kernel_launch entry (invariant)
__device__ int    g_rowstart[NN + 1];
__device__ int    g_fill[NN];
__device__ int2   g_edge[EE];              // CSR: {src col, f32 val}

// packed f32x2 FMA
__device__ __forceinline__ void ffma2f(float2& d, float2 a, float2 b) {
    unsigned long long dd = *(unsigned long long*)&d;
    asm("fma.rn.f32x2 %0, %1, %2, %0;"
        : "+l"(dd) : "l"(*(unsigned long long*)&a), "l"(*(unsigned long long*)&b));
    d = *(float2*)&dd;
}

// ---------------- init h/h16/W16 + edge histogram (counts pre-zeroed) --------
__global__ void init_hist_kernel(const float* __restrict__ x,
                                 const float* __restrict__ W,
                                 const int* __restrict__ erow) {
    int i = blockIdx.x * blockDim.x + threadIdx.x;
    if (i < NN * DD) { float v = x[i]; g_h[i] = v; g_h16[i] = __float2half(v); }
    if (i < DD * DD) g_W16[i] = __float2half(W[i]);
    if (i < EE) atomicAdd(&g_count[erow[i]], 1);
}

__global__ void scan_kernel() {
    __shared__ int part[1024];
    const int CH = (NN + 1023) / 1024;
    int t = threadIdx.x;
    int begin = t * CH;
    int end = begin + CH; if (end > NN) end = NN;
    int s = 0;
    for (int i = begin; i < end; ++i) s += g_count[i];
    part[t] = s;
    __syncthreads();
    for (int off = 1; off < 1024; off <<= 1) {
        int v = (t >= off) ? part[t - off] : 0;
        __syncthreads();
        part[t] += v;
        __syncthreads();
    }
    int running = (t == 0) ? 0 : part[t - 1];
    for (int i = begin; i < end; ++i) {
        g_rowstart[i] = running;
        g_fill[i] = running;
        running += g_count[i];
    }
    if (t == 1023) g_rowstart[NN] = running;  // == EE
}

__global__ void fill_kernel(const int* __restrict__ erow,
                            const int* __restrict__ ecol,
                            const float* __restrict__ ev) {
    int e = blockIdx.x * blockDim.x + threadIdx.x;
    if (e < EE) {
        int r = erow[e];
        int p = atomicAdd(&g_fill[r], 1);
        g_edge[p] = make_int2(ecol[e], __float_as_int(ev[e]));
    }
}

// ---------------- GEMM: support32 = h16 @ W16 (tensor cores, direct store) ---
// 256 threads = 8 warps; warp = one 16-row band. A frags from global h16,
// B = W16 in smem, fp32 accumulators stored straight to global (ld = DD).
__global__ void __launch_bounds__(256) gemm_kernel() {
    __shared__ __half Ws[DD * LDW];   // 19968 B
    int tid = threadIdx.x, wid = tid >> 5;
    int band = blockIdx.x * 8 + wid;

    for (int i = tid; i < DD * DD / 8; i += 256) {
        int r = (i * 8) / DD, c = (i * 8) % DD;
        *(uint4*)&Ws[r * LDW + c] = *(const uint4*)&g_W16[r * DD + c];
    }
    __syncthreads();
    if (band >= NBANDS) return;

    wmma::fragment<wmma::accumulator, 16, 16, 16, float> acc[6];
#pragma unroll
    for (int n = 0; n < 6; ++n) wmma::fill_fragment(acc[n], 0.f);

    const __half* Abase = g_h16 + (size_t)band * 16 * DD;
#pragma unroll
    for (int k = 0; k < 6; ++k) {
        wmma::fragment<wmma::matrix_a, 16, 16, 16, __half, wmma::row_major> af;
        wmma::load_matrix_sync(af, Abase + k * 16, DD);
#pragma unroll
        for (int n = 0; n < 6; ++n) {
            wmma::fragment<wmma::matrix_b, 16, 16, 16, __half, wmma::row_major> bf;
            wmma::load_matrix_sync(bf, Ws + (k * 16) * LDW + n * 16, LDW);
            wmma::mma_sync(acc[n], af, bf, acc[n]);
        }
    }

    float* Obase = g_support32 + (size_t)band * 16 * DD;
#pragma unroll
    for (int n = 0; n < 6; ++n)
        wmma::store_matrix_sync(Obase + n * 16, acc[n], DD, wmma::mem_row_major);
}

// ---------------- aggregation + smooth + ReLU --------------------------------
// One warp per row; 4 edge-groups x 8 feature-owner lanes; float4 gathers.
__global__ void __launch_bounds__(256) agg_kernel(const float* __restrict__ b) {
    int warp = (blockIdx.x * blockDim.x + threadIdx.x) >> 5;
    int lane = threadIdx.x & 31;
    if (warp >= NN) return;
    int grp = lane >> 3;
    int sub = lane & 7;

    int j0 = g_rowstart[warp];
    int j1 = g_rowstart[warp + 1];

    float2 acc[6];
#pragma unroll
    for (int i = 0; i < 6; ++i) acc[i] = make_float2(0.f, 0.f);

    for (int j = j0 + grp; j < j1; j += 4) {
        int2 e = __ldg(&g_edge[j]);
        float v = __int_as_float(e.y);
        float2 vv = make_float2(v, v);
        const float4* s = (const float4*)(g_support32 + (size_t)e.x * DD);
        float4 d0 = __ldg(&s[sub]);
        float4 d1 = __ldg(&s[8 + sub]);
        float4 d2 = __ldg(&s[16 + sub]);
        ffma2f(acc[0], make_float2(d0.x, d0.y), vv);
        ffma2f(acc[1], make_float2(d0.z, d0.w), vv);
        ffma2f(acc[2], make_float2(d1.x, d1.y), vv);
        ffma2f(acc[3], make_float2(d1.z, d1.w), vv);
        ffma2f(acc[4], make_float2(d2.x, d2.y), vv);
        ffma2f(acc[5], make_float2(d2.z, d2.w), vv);
    }

#pragma unroll
    for (int i = 0; i < 6; ++i) {
        acc[i].x += __shfl_xor_sync(0xffffffffu, acc[i].x, 8);
        acc[i].y += __shfl_xor_sync(0xffffffffu, acc[i].y, 8);
        acc[i].x += __shfl_xor_sync(0xffffffffu, acc[i].x, 16);
        acc[i].y += __shfl_xor_sync(0xffffffffu, acc[i].y, 16);
    }

    if (lane < 8) {
        float* hrow = g_h + (size_t)warp * DD;
#pragma unroll
        for (int sg = 0; sg < 3; ++sg) {
            int off = sg * 32 + sub * 4;
            float4 hv = *(float4*)&hrow[off];
            float4 bv = *(const float4*)&b[off];
            float2 a0 = acc[2 * sg];
            float2 a1 = acc[2 * sg + 1];
            hv.x = fmaxf(SMOOTH * hv.x + (1.f - SMOOTH) * (a0.x + bv.x), 0.f);
            hv.y = fmaxf(SMOOTH * hv.y + (1.f - SMOOTH) * (a0.y + bv.y), 0.f);
            hv.z = fmaxf(SMOOTH * hv.z + (1.f - SMOOTH) * (a1.x + bv.z), 0.f);
            hv.w = fmaxf(SMOOTH * hv.w + (1.f - SMOOTH) * (a1.y + bv.w), 0.f);
            *(float4*)&hrow[off] = hv;
            __half2 p0 = __floats2half2_rn(hv.x, hv.y);
            __half2 p1 = __floats2half2_rn(hv.z, hv.w);
            uint2 u; u.x = *(unsigned*)&p0; u.y = *(unsigned*)&p1;
            *(uint2*)&g_h16[(size_t)warp * DD + off] = u;
        }
    }
}

// ---------------- final: logits + log_softmax; re-zero counts for next replay
__global__ void __launch_bounds__(256) out_kernel(const float* __restrict__ Wl,
                                                  float* __restrict__ out) {
    __shared__ float Ws2[DD * CC];
    __shared__ float Hs[32 * DD];
    __shared__ float Ls[32 * CC];
    int tid = threadIdx.x;
    int row0 = blockIdx.x * 32;

    // maintain the g_count==0 invariant for the next kernel_launch call
    int gz = blockIdx.x * blockDim.x + tid;
    if (gz < NN) g_count[gz] = 0;

    for (int i = tid; i < DD * CC; i += 256) Ws2[i] = Wl[i];
    for (int i = tid; i < 32 * DD; i += 256) {
        int r = row0 + i / DD;
        Hs[i] = (r < NN) ? g_h[r * DD + (i % DD)] : 0.f;
    }
    __syncthreads();

    for (int o = tid; o < 32 * CC; o += 256) {
        int r = o / CC, c = o % CC;
        float a = 0.f;
#pragma unroll 4
        for (int k = 0; k < DD; ++k) a += Hs[r * DD + k] * Ws2[k * CC + c];
        Ls[o] = a;
    }
    __syncthreads();

    if (tid < 32) {
        int r = row0 + tid;
        if (r < NN) {
            float m = -1e30f;
#pragma unroll
            for (int c = 0; c < CC; ++c) m = fmaxf(m, Ls[tid * CC + c]);
            float s = 0.f;
#pragma unroll
            for (int c = 0; c < CC; ++c) s += expf(Ls[tid * CC + c] - m);
            float lse = m + logf(s);
#pragma unroll
            for (int c = 0; c < CC; ++c) out[r * CC + c] = Ls[tid * CC + c] - lse;
        }
    }
}

// ---------------- launch ------------------------------------------------------
extern "C" void kernel_launch(void* const* d_in, const int* in_sizes, int n_in,
                              void* d_out, int out_size) {
    (void)in_sizes; (void)n_in; (void)out_size;
    const float* x    = (const float*)d_in[0];
    const int*   erow = (const int*)d_in[1];
    const int*   ecol = (const int*)d_in[2];
    const float* ev   = (const float*)d_in[3];
    const float* Wgc  = (const float*)d_in[4];
    const float* bgc  = (const float*)d_in[5];
    const float* Wlin = (const float*)d_in[6];
    float* out = (float*)d_out;

    init_hist_kernel<<<(NN * DD + 255) / 256, 256>>>(x, Wgc, erow);
    scan_kernel<<<1, 1024>>>();
    fill_kernel<<<(EE + 255) / 256, 256>>>(erow, ecol, ev);

    for (int it = 0; it < NITE; ++it) {
        gemm_kernel<<<(NBANDS + 7) / 8, 256>>>();
        agg_kernel<<<(NN * 32 + 255) / 256, 256>>>(bgc);
    }

    out_kernel<<<(NN + 31) / 32, 256>>>(Wlin, out);
}

// round 9
// speedup vs baseline: 1.6716x; 1.1017x over previous
#include <cuda_runtime.h>
#include <cuda_fp16.h>
#include <math.h>
#include <mma.h>
using namespace nvcuda;

#define NN 50000
#define EE 800000
#define DD 96
#define CC 40
#define NITE 8
#define SMOOTH 0.5f

#define NBANDS ((NN + 15) / 16)   // 3125 (NN % 16 == 0)
#define LDW 104                   // padded half ld for W smem

// ---------------- scratch (device globals; no allocation allowed) ------------
__device__ float  g_h[NN * DD];            // fp32 master features
__device__ __half g_h16[NN * DD];          // fp16 mirror (tensor-core A operand)
__device__ __half g_W16[DD * DD];          // fp16 W_gc
__device__ __half g_support16[NN * DD];    // GEMM out (fp16) / agg gather in
__device__ int    g_count[NN];             // zero at kernel_launch entry (invariant)
__device__ int    g_rowstart[NN + 1];
__device__ int    g_fill[NN];
__device__ int2   g_edge[EE];              // CSR: {src col, f32 val}

// packed f32x2 FMA
__device__ __forceinline__ void ffma2f(float2& d, float2 a, float2 b) {
    unsigned long long dd = *(unsigned long long*)&d;
    asm("fma.rn.f32x2 %0, %1, %2, %0;"
        : "+l"(dd) : "l"(*(unsigned long long*)&a), "l"(*(unsigned long long*)&b));
    d = *(float2*)&dd;
}

// ---------------- init h/h16/W16 + edge histogram (counts pre-zeroed) --------
__global__ void init_hist_kernel(const float* __restrict__ x,
                                 const float* __restrict__ W,
                                 const int* __restrict__ erow) {
    int i = blockIdx.x * blockDim.x + threadIdx.x;
    if (i < NN * DD) { float v = x[i]; g_h[i] = v; g_h16[i] = __float2half(v); }
    if (i < DD * DD) g_W16[i] = __float2half(W[i]);
    if (i < EE) atomicAdd(&g_count[erow[i]], 1);
}

__global__ void scan_kernel() {
    __shared__ int part[1024];
    const int CH = (NN + 1023) / 1024;
    int t = threadIdx.x;
    int begin = t * CH;
    int end = begin + CH; if (end > NN) end = NN;
    int s = 0;
    for (int i = begin; i < end; ++i) s += g_count[i];
    part[t] = s;
    __syncthreads();
    for (int off = 1; off < 1024; off <<= 1) {
        int v = (t >= off) ? part[t - off] : 0;
        __syncthreads();
        part[t] += v;
        __syncthreads();
    }
    int running = (t == 0) ? 0 : part[t - 1];
    for (int i = begin; i < end; ++i) {
        g_rowstart[i] = running;
        g_fill[i] = running;
        running += g_count[i];
    }
    if (t == 1023) g_rowstart[NN] = running;  // == EE
}

__global__ void fill_kernel(const int* __restrict__ erow,
                            const int* __restrict__ ecol,
                            const float* __restrict__ ev) {
    int e = blockIdx.x * blockDim.x + threadIdx.x;
    if (e < EE) {
        int r = erow[e];
        int p = atomicAdd(&g_fill[r], 1);
        g_edge[p] = make_int2(ecol[e], __float_as_int(ev[e]));
    }
}

// ---------------- GEMM: support16 = h16 @ W16 (tensor cores) -----------------
// 8 warps/block, warp = 16-row band. All 6 A fragments prefetched (MLP=6)
// before the mma loop; fp16 accumulators stored DIRECTLY to g_support16.
__global__ void __launch_bounds__(256) gemm_kernel() {
    __shared__ __half Ws[DD * LDW];   // 19968 B
    int tid = threadIdx.x, wid = tid >> 5;
    int band = blockIdx.x * 8 + wid;

    for (int i = tid; i < DD * DD / 8; i += 256) {
        int r = (i * 8) / DD, c = (i * 8) % DD;
        *(uint4*)&Ws[r * LDW + c] = *(const uint4*)&g_W16[r * DD + c];
    }
    __syncthreads();
    if (band >= NBANDS) return;

    // prefetch all A fragments (independent global loads, latency overlapped)
    wmma::fragment<wmma::matrix_a, 16, 16, 16, __half, wmma::row_major> af[6];
    const __half* Abase = g_h16 + (size_t)band * 16 * DD;
#pragma unroll
    for (int k = 0; k < 6; ++k)
        wmma::load_matrix_sync(af[k], Abase + k * 16, DD);

    wmma::fragment<wmma::accumulator, 16, 16, 16, __half> acc[6];
#pragma unroll
    for (int n = 0; n < 6; ++n) wmma::fill_fragment(acc[n], __float2half(0.f));

#pragma unroll
    for (int k = 0; k < 6; ++k) {
#pragma unroll
        for (int n = 0; n < 6; ++n) {
            wmma::fragment<wmma::matrix_b, 16, 16, 16, __half, wmma::row_major> bf;
            wmma::load_matrix_sync(bf, Ws + (k * 16) * LDW + n * 16, LDW);
            wmma::mma_sync(acc[n], af[k], bf, acc[n]);
        }
    }

    __half* Obase = g_support16 + (size_t)band * 16 * DD;
#pragma unroll
    for (int n = 0; n < 6; ++n)
        wmma::store_matrix_sync(Obase + n * 16, acc[n], DD, wmma::mem_row_major);
}

// ---------------- aggregation + smooth + ReLU (R5 body, fp16 gathers) --------
__global__ void __launch_bounds__(256) agg_kernel(const float* __restrict__ b) {
    int warp = (blockIdx.x * blockDim.x + threadIdx.x) >> 5;
    int lane = threadIdx.x & 31;
    if (warp >= NN) return;
    int grp = lane >> 3;
    int sub = lane & 7;

    int j0 = g_rowstart[warp];
    int j1 = g_rowstart[warp + 1];

    float2 acc[6];
#pragma unroll
    for (int i = 0; i < 6; ++i) acc[i] = make_float2(0.f, 0.f);

    for (int j = j0 + grp; j < j1; j += 4) {
        int2 e = __ldg(&g_edge[j]);
        float v = __int_as_float(e.y);
        float2 vv = make_float2(v, v);
        const uint2* s = (const uint2*)(g_support16 + (size_t)e.x * DD);
        uint2 d0 = __ldg(&s[sub]);
        uint2 d1 = __ldg(&s[8 + sub]);
        uint2 d2 = __ldg(&s[16 + sub]);
        float2 f;
        f = __half22float2(*(__half2*)&d0.x); ffma2f(acc[0], f, vv);
        f = __half22float2(*(__half2*)&d0.y); ffma2f(acc[1], f, vv);
        f = __half22float2(*(__half2*)&d1.x); ffma2f(acc[2], f, vv);
        f = __half22float2(*(__half2*)&d1.y); ffma2f(acc[3], f, vv);
        f = __half22float2(*(__half2*)&d2.x); ffma2f(acc[4], f, vv);
        f = __half22float2(*(__half2*)&d2.y); ffma2f(acc[5], f, vv);
    }

#pragma unroll
    for (int i = 0; i < 6; ++i) {
        acc[i].x += __shfl_xor_sync(0xffffffffu, acc[i].x, 8);
        acc[i].y += __shfl_xor_sync(0xffffffffu, acc[i].y, 8);
        acc[i].x += __shfl_xor_sync(0xffffffffu, acc[i].x, 16);
        acc[i].y += __shfl_xor_sync(0xffffffffu, acc[i].y, 16);
    }

    if (lane < 8) {
        float* hrow = g_h + (size_t)warp * DD;
#pragma unroll
        for (int sg = 0; sg < 3; ++sg) {
            int off = sg * 32 + sub * 4;
            float4 hv = *(float4*)&hrow[off];
            float4 bv = *(const float4*)&b[off];
            float2 a0 = acc[2 * sg];
            float2 a1 = acc[2 * sg + 1];
            hv.x = fmaxf(SMOOTH * hv.x + (1.f - SMOOTH) * (a0.x + bv.x), 0.f);
            hv.y = fmaxf(SMOOTH * hv.y + (1.f - SMOOTH) * (a0.y + bv.y), 0.f);
            hv.z = fmaxf(SMOOTH * hv.z + (1.f - SMOOTH) * (a1.x + bv.z), 0.f);
            hv.w = fmaxf(SMOOTH * hv.w + (1.f - SMOOTH) * (a1.y + bv.w), 0.f);
            *(float4*)&hrow[off] = hv;
            __half2 p0 = __floats2half2_rn(hv.x, hv.y);
            __half2 p1 = __floats2half2_rn(hv.z, hv.w);
            uint2 u; u.x = *(unsigned*)&p0; u.y = *(unsigned*)&p1;
            *(uint2*)&g_h16[(size_t)warp * DD + off] = u;
        }
    }
}

// ---------------- final: logits + log_softmax; re-zero counts for next replay
__global__ void __launch_bounds__(256) out_kernel(const float* __restrict__ Wl,
                                                  float* __restrict__ out) {
    __shared__ float Ws2[DD * CC];
    __shared__ float Hs[32 * DD];
    __shared__ float Ls[32 * CC];
    int tid = threadIdx.x;
    int row0 = blockIdx.x * 32;

    // maintain the g_count==0 invariant for the next kernel_launch call
    int gz = blockIdx.x * blockDim.x + tid;
    if (gz < NN) g_count[gz] = 0;

    for (int i = tid; i < DD * CC; i += 256) Ws2[i] = Wl[i];
    for (int i = tid; i < 32 * DD; i += 256) {
        int r = row0 + i / DD;
        Hs[i] = (r < NN) ? g_h[r * DD + (i % DD)] : 0.f;
    }
    __syncthreads();

    for (int o = tid; o < 32 * CC; o += 256) {
        int r = o / CC, c = o % CC;
        float a = 0.f;
#pragma unroll 4
        for (int k = 0; k < DD; ++k) a += Hs[r * DD + k] * Ws2[k * CC + c];
        Ls[o] = a;
    }
    __syncthreads();

    if (tid < 32) {
        int r = row0 + tid;
        if (r < NN) {
            float m = -1e30f;
#pragma unroll
            for (int c = 0; c < CC; ++c) m = fmaxf(m, Ls[tid * CC + c]);
            float s = 0.f;
#pragma unroll
            for (int c = 0; c < CC; ++c) s += expf(Ls[tid * CC + c] - m);
            float lse = m + logf(s);
#pragma unroll
            for (int c = 0; c < CC; ++c) out[r * CC + c] = Ls[tid * CC + c] - lse;
        }
    }
}

// ---------------- launch ------------------------------------------------------
extern "C" void kernel_launch(void* const* d_in, const int* in_sizes, int n_in,
                              void* d_out, int out_size) {
    (void)in_sizes; (void)n_in; (void)out_size;
    const float* x    = (const float*)d_in[0];
    const int*   erow = (const int*)d_in[1];
    const int*   ecol = (const int*)d_in[2];
    const float* ev   = (const float*)d_in[3];
    const float* Wgc  = (const float*)d_in[4];
    const float* bgc  = (const float*)d_in[5];
    const float* Wlin = (const float*)d_in[6];
    float* out = (float*)d_out;

    init_hist_kernel<<<(NN * DD + 255) / 256, 256>>>(x, Wgc, erow);
    scan_kernel<<<1, 1024>>>();
    fill_kernel<<<(EE + 255) / 256, 256>>>(erow, ecol, ev);

    for (int it = 0; it < NITE; ++it) {
        gemm_kernel<<<(NBANDS + 7) / 8, 256>>>();
        agg_kernel<<<(NN * 32 + 255) / 256, 256>>>(bgc);
    }

    out_kernel<<<(NN + 31) / 32, 256>>>(Wlin, out);
}